// round 15
// baseline (speedup 1.0000x reference)
#include <cuda_runtime.h>
#include <cstdint>

#define NODES 100000
#define EDGES 1600000
#define GRAPHS 64
#define D 128
#define ODIM 256
#define LAYERS 5
#define BN_EPS 1e-5f
#define NB 391                 // ceil(NODES/256) scan blocks

#define NTILES ((NODES + 127) / 128)   // 782
#define GEMM_GRID 148
#define PADK 136               // bf16 row stride (pad kills LDS bank conflicts)

// dynamic smem layout (bytes)
#define OFF_SS    0                      // 256 floats (scale1|shift1)
#define OFF_BIAS  1024                   // 128 floats
#define OFF_WH    2048                   // Wt hi  [128][PADK] bf16 = 34816B
#define OFF_WL    (OFF_WH + 34816)
#define OFF_ZH0   (OFF_WL + 34816)       // 71680
#define OFF_ZL0   (OFF_ZH0 + 34816)
#define OFF_ZH1   (OFF_ZL0 + 34816)
#define OFF_ZL1   (OFF_ZH1 + 34816)
#define TS_SMEM   (OFF_ZL1 + 34816)      // 210944

// Scratch (device globals; no runtime allocation)
__device__ float g_H[NODES * D];
__device__ float g_AGG[NODES * D];
__device__ float g_T1[NODES * D];
__device__ float g_stats[4 * D];     // [sum1 | sq1 | sum2 | sq2]
// CSR scratch
__device__ int g_deg[NODES];
__device__ int g_rowstart[NODES + 1];
__device__ int g_cursor[NODES];
__device__ int g_csr[EDGES];
__device__ int g_bsum[NB];
__device__ int g_boff[NB];

// ------------------------------------------------------------ bf16 helpers
__device__ __forceinline__ uint32_t pack_bf2(float a, float b) {   // low=a, high=b
    uint32_t r; asm("cvt.rn.bf16x2.f32 %0, %1, %2;" : "=r"(r) : "f"(b), "f"(a)); return r;
}
__device__ __forceinline__ float bflo(uint32_t h) { return __uint_as_float(h << 16); }
__device__ __forceinline__ float bfhi(uint32_t h) { return __uint_as_float(h & 0xffff0000u); }

__device__ __forceinline__ void mma_bf16(float* d, const uint32_t* a, const uint32_t* b) {
    asm volatile(
        "mma.sync.aligned.m16n8k16.row.col.f32.bf16.bf16.f32 "
        "{%0,%1,%2,%3}, {%4,%5,%6,%7}, {%8,%9}, {%0,%1,%2,%3};"
        : "+f"(d[0]), "+f"(d[1]), "+f"(d[2]), "+f"(d[3])
        : "r"(a[0]), "r"(a[1]), "r"(a[2]), "r"(a[3]), "r"(b[0]), "r"(b[1]));
}

// ---------------------------------------------------------------- utilities
__global__ void init_kernel(const float* __restrict__ src, int n4) {
    int i = blockIdx.x * blockDim.x + threadIdx.x;
    if (i < n4) ((float4*)g_H)[i] = ((const float4*)src)[i];
}

// ------------------------------------------------------------- CSR build
__global__ void zero_deg_kernel() {
    int i = blockIdx.x * blockDim.x + threadIdx.x;
    if (i < NODES) g_deg[i] = 0;
}
__global__ void hist_kernel(const int* __restrict__ ei) {
    int e = blockIdx.x * blockDim.x + threadIdx.x;
    if (e < EDGES) atomicAdd(&g_deg[ei[EDGES + e]], 1);
}
__global__ void blocksum_kernel() {
    __shared__ int s[256];
    int i = blockIdx.x * 256 + threadIdx.x;
    int v = (i < NODES) ? g_deg[i] : 0;
    s[threadIdx.x] = v;
    __syncthreads();
    for (int off = 128; off > 0; off >>= 1) {
        if (threadIdx.x < off) s[threadIdx.x] += s[threadIdx.x + off];
        __syncthreads();
    }
    if (threadIdx.x == 0) g_bsum[blockIdx.x] = s[0];
}
__global__ void scan_bsum_kernel() {
    __shared__ int s[512];
    int t = threadIdx.x;
    int v = (t < NB) ? g_bsum[t] : 0;
    s[t] = v;
    __syncthreads();
    for (int off = 1; off < 512; off <<= 1) {
        int x = (t >= off) ? s[t - off] : 0;
        __syncthreads();
        s[t] += x;
        __syncthreads();
    }
    if (t < NB) g_boff[t] = s[t] - v;   // exclusive
}
__global__ void scan_local_kernel() {
    __shared__ int s[256];
    int i = blockIdx.x * 256 + threadIdx.x;
    int t = threadIdx.x;
    int v = (i < NODES) ? g_deg[i] : 0;
    s[t] = v;
    __syncthreads();
    for (int off = 1; off < 256; off <<= 1) {
        int x = (t >= off) ? s[t - off] : 0;
        __syncthreads();
        s[t] += x;
        __syncthreads();
    }
    if (i < NODES) {
        int start = g_boff[blockIdx.x] + s[t] - v;
        g_rowstart[i] = start;
        g_cursor[i] = start;
    }
    if (blockIdx.x == 0 && t == 0) g_rowstart[NODES] = EDGES;
}
__global__ void fill_kernel(const int* __restrict__ ei) {
    int e = blockIdx.x * blockDim.x + threadIdx.x;
    if (e < EDGES) {
        int dst = ei[EDGES + e];
        int p = atomicAdd(&g_cursor[dst], 1);
        g_csr[p] = ei[e];
    }
}

// --------------------------------------------- gather: z = h + sum(neighbors)
// also zeroes the BN stats accumulators for this layer (block 0)
__global__ void __launch_bounds__(256) gather_kernel() {
    if (blockIdx.x == 0) {
        int t = threadIdx.x;
        g_stats[t] = 0.f;
        g_stats[t + 256] = 0.f;
    }
    int gw = (blockIdx.x * blockDim.x + threadIdx.x) >> 5;
    if (gw >= NODES) return;
    int lane = threadIdx.x & 31;
    int s = g_rowstart[gw];
    int e = g_rowstart[gw + 1];
    float4 acc = *(const float4*)(g_H + (size_t)gw * D + lane * 4);
    for (int base = s; base < e; base += 32) {
        int n = min(32, e - base);
        int myidx = (base + lane < e) ? g_csr[base + lane] : 0;
        for (int t = 0; t < n; t++) {
            int src = __shfl_sync(0xffffffffu, myidx, t);
            float4 v = *(const float4*)(g_H + (size_t)src * D + lane * 4);
            acc.x += v.x; acc.y += v.y; acc.z += v.z; acc.w += v.w;
        }
    }
    *(float4*)(g_AGG + (size_t)gw * D + lane * 4) = acc;
}

// =============================================== tensor-core GEMM (mma.sync, bf16 x3)
// out[r][c] = bias[c] + sum_k act(in[r][k]) * w[k][c]
// A = Z tile (128 x K128 bf16 hi/lo, DOUBLE-BUFFERED), B = W^T (CTA-resident).
// Register prefetch of next tile's fp32 rows overlaps LDG with HMMA.
// 3 passes: AhBh + AhBl + AlBh, fp32 accum. Fused bias + BN column stats.
// ACT=1: computes scale/shift from g_stats[0..255] + gamma/beta in prologue.
template <int ACT, int STATS_OFF>
__global__ void __launch_bounds__(256)
tgemm_kernel(const float* __restrict__ in, const float* __restrict__ w,
             const float* __restrict__ bias, float* __restrict__ out,
             const float* __restrict__ gamma, const float* __restrict__ beta) {
    extern __shared__ char smem[];
    const int tid = threadIdx.x;
    const int wid = tid >> 5;
    const int lane = tid & 31;
    const int g8 = lane >> 2;          // 0..7
    const int kp = (lane & 3) * 2;     // 0,2,4,6

    uint16_t* WH = (uint16_t*)(smem + OFF_WH);
    uint16_t* WL = (uint16_t*)(smem + OFF_WL);
    uint16_t* ZHb[2] = {(uint16_t*)(smem + OFF_ZH0), (uint16_t*)(smem + OFF_ZH1)};
    uint16_t* ZLb[2] = {(uint16_t*)(smem + OFF_ZL0), (uint16_t*)(smem + OFF_ZL1)};
    float* biasS = (float*)(smem + OFF_BIAS);
    float* ssS   = (float*)(smem + OFF_SS);

    if (ACT && tid < D) {
        float m = g_stats[tid] * (1.0f / NODES);
        float v = g_stats[D + tid] * (1.0f / NODES) - m * m;
        float sc = gamma[tid] * rsqrtf(v + BN_EPS);
        ssS[tid] = sc;
        ssS[D + tid] = beta[tid] - m * sc;
    }
    if (tid < D) biasS[tid] = bias[tid];

    // ---- W prologue: transpose + hi/lo bf16 split (once per CTA) ----
    {
        const int c = tid & 127;
        const int khW = (tid >> 7) << 6;    // 0 or 64
        #pragma unroll 8
        for (int i = 0; i < 32; i++) {
            int k = khW + 2 * i;
            float w0 = w[(size_t)k * D + c];
            float w1 = w[(size_t)(k + 1) * D + c];
            uint32_t h = pack_bf2(w0, w1);
            uint32_t l = pack_bf2(w0 - bflo(h), w1 - bfhi(h));
            *(uint32_t*)(WH + c * PADK + k) = h;
            *(uint32_t*)(WL + c * PADK + k) = l;
        }
    }

    const int warp_r = wid >> 1;        // 0..3  (row group of 32)
    const int warp_c = wid & 1;         // 0..1  (col group of 64)
    const int rZ = tid >> 1;            // staging row 0..127
    const int khZ = (tid & 1) << 6;     // staging k half

    float csum[16], csq[16];
    #pragma unroll
    for (int i = 0; i < 16; i++) { csum[i] = 0.f; csq[i] = 0.f; }

    // ---- stage first tile directly (both halves) into buffer 0 ----
    {
        const int tbase = blockIdx.x * 128;
        int row = tbase + rZ;
        bool valid = row < NODES;
        uint16_t* ZH = ZHb[0];
        uint16_t* ZL = ZLb[0];
        if (ACT) __syncthreads();    // ssS ready before use
        #pragma unroll 4
        for (int i = 0; i < 16; i++) {
            int k0 = khZ + i * 4;
            float4 f = make_float4(0.f, 0.f, 0.f, 0.f);
            if (valid) {
                f = *(const float4*)(in + (size_t)row * D + k0);
                if (ACT) {
                    float4 sA = *(const float4*)(ssS + k0);
                    float4 sB = *(const float4*)(ssS + 128 + k0);
                    f.x = fmaxf(fmaf(sA.x, f.x, sB.x), 0.f);
                    f.y = fmaxf(fmaf(sA.y, f.y, sB.y), 0.f);
                    f.z = fmaxf(fmaf(sA.z, f.z, sB.z), 0.f);
                    f.w = fmaxf(fmaf(sA.w, f.w, sB.w), 0.f);
                }
            }
            uint32_t h01 = pack_bf2(f.x, f.y);
            uint32_t h23 = pack_bf2(f.z, f.w);
            uint32_t l01 = pack_bf2(f.x - bflo(h01), f.y - bfhi(h01));
            uint32_t l23 = pack_bf2(f.z - bflo(h23), f.w - bfhi(h23));
            *(unsigned long long*)(ZH + rZ * PADK + k0) =
                ((unsigned long long)h23 << 32) | h01;
            *(unsigned long long*)(ZL + rZ * PADK + k0) =
                ((unsigned long long)l23 << 32) | l01;
        }
    }
    __syncthreads();

    int cur = 0;
    for (int tile = blockIdx.x; tile < NTILES; tile += GEMM_GRID, cur ^= 1) {
        const int tbase = tile * 128;
        const int next = tile + GEMM_GRID;
        const bool has_next = next < NTILES;
        const int nrow = next * 128 + rZ;
        const bool nvalid = has_next && (nrow < NODES);
        uint16_t* ZH = ZHb[cur];
        uint16_t* ZL = ZLb[cur];
        uint16_t* ZHn = ZHb[cur ^ 1];
        uint16_t* ZLn = ZLb[cur ^ 1];

        float4 pf[8];

        // ---- init D with bias ----
        float d[2][8][4];
        #pragma unroll
        for (int nt = 0; nt < 8; nt++) {
            float2 bv = *(const float2*)(biasS + warp_c * 64 + nt * 8 + kp);
            #pragma unroll
            for (int mt = 0; mt < 2; mt++) {
                d[mt][nt][0] = bv.x; d[mt][nt][1] = bv.y;
                d[mt][nt][2] = bv.x; d[mt][nt][3] = bv.y;
            }
        }

        const int ra = warp_r * 32 + g8;

        // ================= first half: prefetch h0, MMA kc 0..3, STS h0 =====
        if (has_next) {
            #pragma unroll
            for (int i = 0; i < 8; i++) {
                int k0 = khZ + i * 4;
                pf[i] = nvalid ? *(const float4*)(in + (size_t)nrow * D + k0)
                               : make_float4(0.f, 0.f, 0.f, 0.f);
            }
        }
        #pragma unroll
        for (int kc = 0; kc < 4; kc++) {
            const int k0 = kc * 16;
            uint32_t ah[2][4], al[2][4];
            #pragma unroll
            for (int mt = 0; mt < 2; mt++) {
                const uint16_t* zr0 = ZH + (ra + mt * 16) * PADK + k0 + kp;
                ah[mt][0] = *(const uint32_t*)(zr0);
                ah[mt][1] = *(const uint32_t*)(zr0 + 8 * PADK);
                ah[mt][2] = *(const uint32_t*)(zr0 + 8);
                ah[mt][3] = *(const uint32_t*)(zr0 + 8 * PADK + 8);
                const uint16_t* zl0 = ZL + (ra + mt * 16) * PADK + k0 + kp;
                al[mt][0] = *(const uint32_t*)(zl0);
                al[mt][1] = *(const uint32_t*)(zl0 + 8 * PADK);
                al[mt][2] = *(const uint32_t*)(zl0 + 8);
                al[mt][3] = *(const uint32_t*)(zl0 + 8 * PADK + 8);
            }
            #pragma unroll
            for (int nt = 0; nt < 8; nt++) {
                int n = warp_c * 64 + nt * 8 + g8;
                uint32_t bh[2], bl[2];
                const uint16_t* wr = WH + n * PADK + k0 + kp;
                bh[0] = *(const uint32_t*)(wr);
                bh[1] = *(const uint32_t*)(wr + 8);
                const uint16_t* wl = WL + n * PADK + k0 + kp;
                bl[0] = *(const uint32_t*)(wl);
                bl[1] = *(const uint32_t*)(wl + 8);
                mma_bf16(d[0][nt], ah[0], bh);
                mma_bf16(d[1][nt], ah[1], bh);
                mma_bf16(d[0][nt], ah[0], bl);
                mma_bf16(d[1][nt], ah[1], bl);
                mma_bf16(d[0][nt], al[0], bh);
                mma_bf16(d[1][nt], al[1], bh);
            }
        }
        if (has_next) {
            #pragma unroll
            for (int i = 0; i < 8; i++) {
                int k0 = khZ + i * 4;
                float4 f = pf[i];
                if (ACT && nvalid) {
                    float4 sA = *(const float4*)(ssS + k0);
                    float4 sB = *(const float4*)(ssS + 128 + k0);
                    f.x = fmaxf(fmaf(sA.x, f.x, sB.x), 0.f);
                    f.y = fmaxf(fmaf(sA.y, f.y, sB.y), 0.f);
                    f.z = fmaxf(fmaf(sA.z, f.z, sB.z), 0.f);
                    f.w = fmaxf(fmaf(sA.w, f.w, sB.w), 0.f);
                }
                uint32_t h01 = pack_bf2(f.x, f.y);
                uint32_t h23 = pack_bf2(f.z, f.w);
                uint32_t l01 = pack_bf2(f.x - bflo(h01), f.y - bfhi(h01));
                uint32_t l23 = pack_bf2(f.z - bflo(h23), f.w - bfhi(h23));
                *(unsigned long long*)(ZHn + rZ * PADK + k0) =
                    ((unsigned long long)h23 << 32) | h01;
                *(unsigned long long*)(ZLn + rZ * PADK + k0) =
                    ((unsigned long long)l23 << 32) | l01;
            }
        }

        // ================= second half: prefetch h1, MMA kc 4..7, STS h1 ====
        if (has_next) {
            #pragma unroll
            for (int i = 0; i < 8; i++) {
                int k0 = khZ + (i + 8) * 4;
                pf[i] = nvalid ? *(const float4*)(in + (size_t)nrow * D + k0)
                               : make_float4(0.f, 0.f, 0.f, 0.f);
            }
        }
        #pragma unroll
        for (int kc = 4; kc < 8; kc++) {
            const int k0 = kc * 16;
            uint32_t ah[2][4], al[2][4];
            #pragma unroll
            for (int mt = 0; mt < 2; mt++) {
                const uint16_t* zr0 = ZH + (ra + mt * 16) * PADK + k0 + kp;
                ah[mt][0] = *(const uint32_t*)(zr0);
                ah[mt][1] = *(const uint32_t*)(zr0 + 8 * PADK);
                ah[mt][2] = *(const uint32_t*)(zr0 + 8);
                ah[mt][3] = *(const uint32_t*)(zr0 + 8 * PADK + 8);
                const uint16_t* zl0 = ZL + (ra + mt * 16) * PADK + k0 + kp;
                al[mt][0] = *(const uint32_t*)(zl0);
                al[mt][1] = *(const uint32_t*)(zl0 + 8 * PADK);
                al[mt][2] = *(const uint32_t*)(zl0 + 8);
                al[mt][3] = *(const uint32_t*)(zl0 + 8 * PADK + 8);
            }
            #pragma unroll
            for (int nt = 0; nt < 8; nt++) {
                int n = warp_c * 64 + nt * 8 + g8;
                uint32_t bh[2], bl[2];
                const uint16_t* wr = WH + n * PADK + k0 + kp;
                bh[0] = *(const uint32_t*)(wr);
                bh[1] = *(const uint32_t*)(wr + 8);
                const uint16_t* wl = WL + n * PADK + k0 + kp;
                bl[0] = *(const uint32_t*)(wl);
                bl[1] = *(const uint32_t*)(wl + 8);
                mma_bf16(d[0][nt], ah[0], bh);
                mma_bf16(d[1][nt], ah[1], bh);
                mma_bf16(d[0][nt], ah[0], bl);
                mma_bf16(d[1][nt], ah[1], bl);
                mma_bf16(d[0][nt], al[0], bh);
                mma_bf16(d[1][nt], al[1], bh);
            }
        }
        if (has_next) {
            #pragma unroll
            for (int i = 0; i < 8; i++) {
                int k0 = khZ + (i + 8) * 4;
                float4 f = pf[i];
                if (ACT && nvalid) {
                    float4 sA = *(const float4*)(ssS + k0);
                    float4 sB = *(const float4*)(ssS + 128 + k0);
                    f.x = fmaxf(fmaf(sA.x, f.x, sB.x), 0.f);
                    f.y = fmaxf(fmaf(sA.y, f.y, sB.y), 0.f);
                    f.z = fmaxf(fmaf(sA.z, f.z, sB.z), 0.f);
                    f.w = fmaxf(fmaf(sA.w, f.w, sB.w), 0.f);
                }
                uint32_t h01 = pack_bf2(f.x, f.y);
                uint32_t h23 = pack_bf2(f.z, f.w);
                uint32_t l01 = pack_bf2(f.x - bflo(h01), f.y - bfhi(h01));
                uint32_t l23 = pack_bf2(f.z - bflo(h23), f.w - bfhi(h23));
                *(unsigned long long*)(ZHn + rZ * PADK + k0) =
                    ((unsigned long long)h23 << 32) | h01;
                *(unsigned long long*)(ZLn + rZ * PADK + k0) =
                    ((unsigned long long)l23 << 32) | l01;
            }
        }

        // ---- epilogue: STG.128 via lane pairing + BN stats ----
        #pragma unroll
        for (int mt = 0; mt < 2; mt++) {
            int row = tbase + warp_r * 32 + mt * 16 + g8;
            #pragma unroll
            for (int nt = 0; nt < 8; nt++) {
                float* dd = d[mt][nt];
                if (row < NODES) {
                    csum[nt * 2]     += dd[0]; csq[nt * 2]     += dd[0] * dd[0];
                    csum[nt * 2 + 1] += dd[1]; csq[nt * 2 + 1] += dd[1] * dd[1];
                }
                if (row + 8 < NODES) {
                    csum[nt * 2]     += dd[2]; csq[nt * 2]     += dd[2] * dd[2];
                    csum[nt * 2 + 1] += dd[3]; csq[nt * 2 + 1] += dd[3] * dd[3];
                }
                float tx = (lane & 1) ? dd[0] : dd[2];
                float ty = (lane & 1) ? dd[1] : dd[3];
                float rx = __shfl_xor_sync(0xffffffffu, tx, 1);
                float ry = __shfl_xor_sync(0xffffffffu, ty, 1);
                if (!(lane & 1)) {   // kp in {0,4}: store row r, cols kp..kp+3
                    if (row < NODES) {
                        int col = warp_c * 64 + nt * 8 + kp;
                        *(float4*)(out + (size_t)row * D + col) =
                            make_float4(dd[0], dd[1], rx, ry);
                    }
                } else {             // kp in {2,6}: store row r+8, cols kp-2..kp+1
                    if (row + 8 < NODES) {
                        int col = warp_c * 64 + nt * 8 + kp - 2;
                        *(float4*)(out + (size_t)(row + 8) * D + col) =
                            make_float4(rx, ry, dd[2], dd[3]);
                    }
                }
            }
        }
        __syncthreads();   // next buffer fully staged; cur buffer reads done
    }

    // ---- stats: reduce over the 8 lanes sharing each column, then atomics ----
    #pragma unroll
    for (int i = 0; i < 16; i++) {
        float s = csum[i], q = csq[i];
        s += __shfl_xor_sync(0xffffffffu, s, 4);
        s += __shfl_xor_sync(0xffffffffu, s, 8);
        s += __shfl_xor_sync(0xffffffffu, s, 16);
        q += __shfl_xor_sync(0xffffffffu, q, 4);
        q += __shfl_xor_sync(0xffffffffu, q, 8);
        q += __shfl_xor_sync(0xffffffffu, q, 16);
        if (lane < 4) {
            int col = warp_c * 64 + (i >> 1) * 8 + lane * 2 + (i & 1);
            atomicAdd(&g_stats[STATS_OFF + col], s);
            atomicAdd(&g_stats[STATS_OFF + D + col], q);
        }
    }
}

// ---------------------- residual: h += relu(bn2(t2)) (BN computed in-block)
__global__ void __launch_bounds__(256)
residual_kernel(const float* __restrict__ t2, float* __restrict__ out_node,
                const float* __restrict__ gamma, const float* __restrict__ beta) {
    __shared__ float ss[256];
    int tid = threadIdx.x;
    if (tid < D) {
        float m = g_stats[2 * D + tid] * (1.0f / NODES);
        float v = g_stats[3 * D + tid] * (1.0f / NODES) - m * m;
        float sc = gamma[tid] * rsqrtf(v + BN_EPS);
        ss[tid] = sc;
        ss[D + tid] = beta[tid] - m * sc;
    }
    __syncthreads();
    int i = blockIdx.x * blockDim.x + tid;   // float4 index
    if (i >= NODES * (D / 4)) return;
    int c4 = (i & 31) * 4;
    float4 sc = *(const float4*)&ss[c4];
    float4 sh = *(const float4*)&ss[D + c4];
    float4 t = ((const float4*)t2)[i];
    float4 h = ((float4*)g_H)[i];
    h.x += fmaxf(fmaf(sc.x, t.x, sh.x), 0.f);
    h.y += fmaxf(fmaf(sc.y, t.y, sh.y), 0.f);
    h.z += fmaxf(fmaf(sc.z, t.z, sh.z), 0.f);
    h.w += fmaxf(fmaf(sc.w, t.w, sh.w), 0.f);
    ((float4*)g_H)[i] = h;
    if (out_node) ((float4*)out_node)[i] = h;
}

// ------------------------------- fused mean pool (batch sorted) + projection
__global__ void poolproj_kernel(const int* __restrict__ batch,
                                const float* __restrict__ wp,
                                const float* __restrict__ bp,
                                float* __restrict__ out) {
    int g = blockIdx.x;
    int lo = 0, hi_s = NODES;
    while (lo < hi_s) { int mid = (lo + hi_s) >> 1; if (batch[mid] < g) lo = mid + 1; else hi_s = mid; }
    int start = lo;
    lo = 0; hi_s = NODES;
    while (lo < hi_s) { int mid = (lo + hi_s) >> 1; if (batch[mid] < g + 1) lo = mid + 1; else hi_s = mid; }
    int end = lo;

    __shared__ float part[256];
    __shared__ float prow[D];
    int col = threadIdx.x & 127;
    int half = threadIdx.x >> 7;   // 0/1
    float s = 0.f;
    for (int row = start + half; row < end; row += 2)
        s += g_H[(size_t)row * D + col];
    part[threadIdx.x] = s;
    __syncthreads();
    if (threadIdx.x < 128) {
        float tot = part[threadIdx.x] + part[threadIdx.x + 128];
        float cnt = (float)(end - start);
        prow[threadIdx.x] = tot / fmaxf(cnt, 1.f);
    }
    __syncthreads();
    int c = threadIdx.x;   // 0..255
    float acc = bp[c];
    #pragma unroll
    for (int k = 0; k < D; k++) acc = fmaf(prow[k], wp[k * ODIM + c], acc);
    out[g * ODIM + c] = acc;
}

// ================================================================= launch
extern "C" void kernel_launch(void* const* d_in, const int* in_sizes, int n_in,
                              void* d_out, int out_size) {
    const float* x        = (const float*)d_in[0];
    const int*   ei       = (const int*)d_in[1];     // int32
    const int*   batch    = (const int*)d_in[2];     // int32
    const float* w1       = (const float*)d_in[3];
    const float* b1       = (const float*)d_in[4];
    const float* gamma1   = (const float*)d_in[5];
    const float* beta1    = (const float*)d_in[6];
    const float* w2       = (const float*)d_in[7];
    const float* b2       = (const float*)d_in[8];
    const float* gamma_bn = (const float*)d_in[9];
    const float* beta_bn  = (const float*)d_in[10];
    const float* wp       = (const float*)d_in[11];
    const float* bp       = (const float*)d_in[12];
    float* out = (float*)d_out;

    float *H, *AGG, *T1;
    cudaGetSymbolAddress((void**)&H, g_H);
    cudaGetSymbolAddress((void**)&AGG, g_AGG);
    cudaGetSymbolAddress((void**)&T1, g_T1);

    cudaFuncSetAttribute(tgemm_kernel<0, 0>,
                         cudaFuncAttributeMaxDynamicSharedMemorySize, TS_SMEM);
    cudaFuncSetAttribute(tgemm_kernel<1, 2 * D>,
                         cudaFuncAttributeMaxDynamicSharedMemorySize, TS_SMEM);

    const int n4 = NODES * (D / 4);
    const int cpGrid = (n4 + 255) / 256;
    const int edgeGrid = (EDGES + 255) / 256;

    // h = x
    init_kernel<<<cpGrid, 256>>>(x, n4);

    // ---- build CSR (dst -> list of src), once per launch ----
    zero_deg_kernel<<<NB, 256>>>();
    hist_kernel<<<edgeGrid, 256>>>(ei);
    blocksum_kernel<<<NB, 256>>>();
    scan_bsum_kernel<<<1, 512>>>();
    scan_local_kernel<<<NB, 256>>>();
    fill_kernel<<<edgeGrid, 256>>>(ei);

    for (int i = 0; i < LAYERS; i++) {
        // z = h + sum_neighbors (CSR gather, no atomics); zeroes stats
        gather_kernel<<<(NODES * 32 + 255) / 256, 256>>>();
        // t1 = z @ w1 + b1  (tensor cores; stats -> sum1/sq1)
        tgemm_kernel<0, 0><<<GEMM_GRID, 256, TS_SMEM>>>(
            AGG, w1 + i * D * D, b1 + i * D, T1, nullptr, nullptr);
        // t2 = relu(bn1(t1)) @ w2 + b2  (bn1 computed in prologue; stats -> sum2/sq2)
        tgemm_kernel<1, 2 * D><<<GEMM_GRID, 256, TS_SMEM>>>(
            T1, w2 + i * D * D, b2 + i * D, AGG, gamma1 + i * D, beta1 + i * D);
        // h += relu(bn2(t2)) (bn2 computed in-block); last layer writes node_emb
        float* out_node = (i == LAYERS - 1) ? (out + GRAPHS * ODIM) : nullptr;
        residual_kernel<<<cpGrid, 256>>>(AGG, out_node, gamma_bn + i * D, beta_bn + i * D);
    }

    poolproj_kernel<<<GRAPHS, 256>>>(batch, wp, bp, out);
}

// round 16
// speedup vs baseline: 1.0851x; 1.0851x over previous
#include <cuda_runtime.h>
#include <cstdint>

#define NODES 100000
#define EDGES 1600000
#define GRAPHS 64
#define D 128
#define ODIM 256
#define LAYERS 5
#define BN_EPS 1e-5f
#define NB 391                 // ceil(NODES/256) scan blocks

#define TROWS 64                          // rows per GEMM tile
#define NTILES ((NODES + TROWS - 1) / TROWS)   // 1563
#define GEMM_GRID 296                     // 2 CTAs/SM
#define PADK 136               // bf16 row stride (pad kills LDS bank conflicts)

// dynamic smem layout (bytes)
#define OFF_SS    0                      // 256 floats (scale1|shift1)
#define OFF_BIAS  1024                   // 128 floats
#define OFF_WH    2048                   // Wt hi  [128][PADK] bf16 = 34816B
#define OFF_WL    (OFF_WH + 34816)
#define OFF_ZH    (OFF_WL + 34816)       // [64][PADK] bf16 = 17408B
#define OFF_ZL    (OFF_ZH + 17408)
#define TS_SMEM   (OFF_ZL + 17408)       // 106496 (~104KB) -> 2 CTAs/SM

// Scratch (device globals; no runtime allocation)
__device__ float g_H[NODES * D];
__device__ float g_AGG[NODES * D];
__device__ float g_T1[NODES * D];
__device__ float g_stats[4 * D];     // [sum1 | sq1 | sum2 | sq2]
// CSR scratch
__device__ int g_deg[NODES];
__device__ int g_rowstart[NODES + 1];
__device__ int g_cursor[NODES];
__device__ int g_csr[EDGES];
__device__ int g_bsum[NB];
__device__ int g_boff[NB];

// ------------------------------------------------------------ bf16 helpers
__device__ __forceinline__ uint32_t pack_bf2(float a, float b) {   // low=a, high=b
    uint32_t r; asm("cvt.rn.bf16x2.f32 %0, %1, %2;" : "=r"(r) : "f"(b), "f"(a)); return r;
}
__device__ __forceinline__ float bflo(uint32_t h) { return __uint_as_float(h << 16); }
__device__ __forceinline__ float bfhi(uint32_t h) { return __uint_as_float(h & 0xffff0000u); }

__device__ __forceinline__ void mma_bf16(float* d, const uint32_t* a, const uint32_t* b) {
    asm volatile(
        "mma.sync.aligned.m16n8k16.row.col.f32.bf16.bf16.f32 "
        "{%0,%1,%2,%3}, {%4,%5,%6,%7}, {%8,%9}, {%0,%1,%2,%3};"
        : "+f"(d[0]), "+f"(d[1]), "+f"(d[2]), "+f"(d[3])
        : "r"(a[0]), "r"(a[1]), "r"(a[2]), "r"(a[3]), "r"(b[0]), "r"(b[1]));
}

// ---------------------------------------------------------------- utilities
__global__ void init_kernel(const float* __restrict__ src, int n4) {
    int i = blockIdx.x * blockDim.x + threadIdx.x;
    if (i < n4) ((float4*)g_H)[i] = ((const float4*)src)[i];
}

// ------------------------------------------------------------- CSR build
__global__ void zero_deg_kernel() {
    int i = blockIdx.x * blockDim.x + threadIdx.x;
    if (i < NODES) g_deg[i] = 0;
}
__global__ void hist_kernel(const int* __restrict__ ei) {
    int e = blockIdx.x * blockDim.x + threadIdx.x;
    if (e < EDGES) atomicAdd(&g_deg[ei[EDGES + e]], 1);
}
__global__ void blocksum_kernel() {
    __shared__ int s[256];
    int i = blockIdx.x * 256 + threadIdx.x;
    int v = (i < NODES) ? g_deg[i] : 0;
    s[threadIdx.x] = v;
    __syncthreads();
    for (int off = 128; off > 0; off >>= 1) {
        if (threadIdx.x < off) s[threadIdx.x] += s[threadIdx.x + off];
        __syncthreads();
    }
    if (threadIdx.x == 0) g_bsum[blockIdx.x] = s[0];
}
__global__ void scan_bsum_kernel() {
    __shared__ int s[512];
    int t = threadIdx.x;
    int v = (t < NB) ? g_bsum[t] : 0;
    s[t] = v;
    __syncthreads();
    for (int off = 1; off < 512; off <<= 1) {
        int x = (t >= off) ? s[t - off] : 0;
        __syncthreads();
        s[t] += x;
        __syncthreads();
    }
    if (t < NB) g_boff[t] = s[t] - v;   // exclusive
}
__global__ void scan_local_kernel() {
    __shared__ int s[256];
    int i = blockIdx.x * 256 + threadIdx.x;
    int t = threadIdx.x;
    int v = (i < NODES) ? g_deg[i] : 0;
    s[t] = v;
    __syncthreads();
    for (int off = 1; off < 256; off <<= 1) {
        int x = (t >= off) ? s[t - off] : 0;
        __syncthreads();
        s[t] += x;
        __syncthreads();
    }
    if (i < NODES) {
        int start = g_boff[blockIdx.x] + s[t] - v;
        g_rowstart[i] = start;
        g_cursor[i] = start;
    }
    if (blockIdx.x == 0 && t == 0) g_rowstart[NODES] = EDGES;
}
__global__ void fill_kernel(const int* __restrict__ ei) {
    int e = blockIdx.x * blockDim.x + threadIdx.x;
    if (e < EDGES) {
        int dst = ei[EDGES + e];
        int p = atomicAdd(&g_cursor[dst], 1);
        g_csr[p] = ei[e];
    }
}

// --------------------------------------------- gather: z = h + sum(neighbors)
// also zeroes the BN stats accumulators for this layer (block 0)
__global__ void __launch_bounds__(256) gather_kernel() {
    if (blockIdx.x == 0) {
        int t = threadIdx.x;
        g_stats[t] = 0.f;
        g_stats[t + 256] = 0.f;
    }
    int gw = (blockIdx.x * blockDim.x + threadIdx.x) >> 5;
    if (gw >= NODES) return;
    int lane = threadIdx.x & 31;
    int s = g_rowstart[gw];
    int e = g_rowstart[gw + 1];
    float4 acc = *(const float4*)(g_H + (size_t)gw * D + lane * 4);
    for (int base = s; base < e; base += 32) {
        int n = min(32, e - base);
        int myidx = (base + lane < e) ? g_csr[base + lane] : 0;
        for (int t = 0; t < n; t++) {
            int src = __shfl_sync(0xffffffffu, myidx, t);
            float4 v = *(const float4*)(g_H + (size_t)src * D + lane * 4);
            acc.x += v.x; acc.y += v.y; acc.z += v.z; acc.w += v.w;
        }
    }
    *(float4*)(g_AGG + (size_t)gw * D + lane * 4) = acc;
}

// =============================================== tensor-core GEMM (mma.sync, bf16 x3)
// out[r][c] = bias[c] + sum_k act(in[r][k]) * w[k][c]
// Tile: 64 rows x 128 cols. smem ~104KB -> 2 CTAs/SM; cross-CTA overlap of
// staging (LSU) with MMA (tensor). A = Z tile (bf16 hi/lo), B = W^T resident.
// 3 passes: AhBh + AhBl + AlBh, fp32 accum. Fused bias + BN column stats.
// ACT=1: computes scale/shift from g_stats[0..255] + gamma/beta in prologue.
template <int ACT, int STATS_OFF>
__global__ void __launch_bounds__(256)
tgemm_kernel(const float* __restrict__ in, const float* __restrict__ w,
             const float* __restrict__ bias, float* __restrict__ out,
             const float* __restrict__ gamma, const float* __restrict__ beta) {
    extern __shared__ char smem[];
    const int tid = threadIdx.x;
    const int wid = tid >> 5;
    const int lane = tid & 31;
    const int g8 = lane >> 2;          // 0..7
    const int kp = (lane & 3) * 2;     // 0,2,4,6

    uint16_t* WH = (uint16_t*)(smem + OFF_WH);
    uint16_t* WL = (uint16_t*)(smem + OFF_WL);
    uint16_t* ZH = (uint16_t*)(smem + OFF_ZH);
    uint16_t* ZL = (uint16_t*)(smem + OFF_ZL);
    float* biasS = (float*)(smem + OFF_BIAS);
    float* ssS   = (float*)(smem + OFF_SS);

    if (ACT && tid < D) {
        float m = g_stats[tid] * (1.0f / NODES);
        float v = g_stats[D + tid] * (1.0f / NODES) - m * m;
        float sc = gamma[tid] * rsqrtf(v + BN_EPS);
        ssS[tid] = sc;
        ssS[D + tid] = beta[tid] - m * sc;
    }
    if (tid < D) biasS[tid] = bias[tid];

    // ---- W prologue: transpose + hi/lo bf16 split (once per CTA) ----
    {
        const int c = tid & 127;
        const int khW = (tid >> 7) << 6;    // 0 or 64
        #pragma unroll 8
        for (int i = 0; i < 32; i++) {
            int k = khW + 2 * i;
            float w0 = w[(size_t)k * D + c];
            float w1 = w[(size_t)(k + 1) * D + c];
            uint32_t h = pack_bf2(w0, w1);
            uint32_t l = pack_bf2(w0 - bflo(h), w1 - bfhi(h));
            *(uint32_t*)(WH + c * PADK + k) = h;
            *(uint32_t*)(WL + c * PADK + k) = l;
        }
    }

    const int warp_r = wid >> 1;        // 0..3  (16-row group)
    const int warp_c = wid & 1;         // 0..1  (64-col group)
    const int rZ = tid >> 2;            // staging row 0..63
    const int kqZ = (tid & 3) << 5;     // staging k quarter (32 floats)

    float csum[16], csq[16];
    #pragma unroll
    for (int i = 0; i < 16; i++) { csum[i] = 0.f; csq[i] = 0.f; }

    __syncthreads();   // W / bias / ss ready

    for (int tile = blockIdx.x; tile < NTILES; tile += GEMM_GRID) {
        const int tbase = tile * TROWS;
        // ---- stage Z tile: fp32 -> bf16 hi/lo (ACT fused) ----
        {
            int row = tbase + rZ;
            bool valid = row < NODES;
            #pragma unroll
            for (int i = 0; i < 8; i++) {
                int k0 = kqZ + i * 4;
                float4 f = make_float4(0.f, 0.f, 0.f, 0.f);
                if (valid) {
                    f = *(const float4*)(in + (size_t)row * D + k0);
                    if (ACT) {
                        float4 sA = *(const float4*)(ssS + k0);
                        float4 sB = *(const float4*)(ssS + 128 + k0);
                        f.x = fmaxf(fmaf(sA.x, f.x, sB.x), 0.f);
                        f.y = fmaxf(fmaf(sA.y, f.y, sB.y), 0.f);
                        f.z = fmaxf(fmaf(sA.z, f.z, sB.z), 0.f);
                        f.w = fmaxf(fmaf(sA.w, f.w, sB.w), 0.f);
                    }
                }
                uint32_t h01 = pack_bf2(f.x, f.y);
                uint32_t h23 = pack_bf2(f.z, f.w);
                uint32_t l01 = pack_bf2(f.x - bflo(h01), f.y - bfhi(h01));
                uint32_t l23 = pack_bf2(f.z - bflo(h23), f.w - bfhi(h23));
                *(unsigned long long*)(ZH + rZ * PADK + k0) =
                    ((unsigned long long)h23 << 32) | h01;
                *(unsigned long long*)(ZL + rZ * PADK + k0) =
                    ((unsigned long long)l23 << 32) | l01;
            }
        }
        __syncthreads();

        // ---- init D with bias ----
        float d[8][4];
        #pragma unroll
        for (int nt = 0; nt < 8; nt++) {
            float2 bv = *(const float2*)(biasS + warp_c * 64 + nt * 8 + kp);
            d[nt][0] = bv.x; d[nt][1] = bv.y;
            d[nt][2] = bv.x; d[nt][3] = bv.y;
        }

        // ---- K loop: 8 chunks of 16; 3 passes fused per chunk ----
        const int ra = warp_r * 16 + g8;
        #pragma unroll 2
        for (int kc = 0; kc < 8; kc++) {
            const int k0 = kc * 16;
            uint32_t ah[4], al[4];
            {
                const uint16_t* zr0 = ZH + ra * PADK + k0 + kp;
                ah[0] = *(const uint32_t*)(zr0);
                ah[1] = *(const uint32_t*)(zr0 + 8 * PADK);
                ah[2] = *(const uint32_t*)(zr0 + 8);
                ah[3] = *(const uint32_t*)(zr0 + 8 * PADK + 8);
                const uint16_t* zl0 = ZL + ra * PADK + k0 + kp;
                al[0] = *(const uint32_t*)(zl0);
                al[1] = *(const uint32_t*)(zl0 + 8 * PADK);
                al[2] = *(const uint32_t*)(zl0 + 8);
                al[3] = *(const uint32_t*)(zl0 + 8 * PADK + 8);
            }
            #pragma unroll
            for (int nt = 0; nt < 8; nt++) {
                int n = warp_c * 64 + nt * 8 + g8;
                uint32_t bh[2], bl[2];
                const uint16_t* wr = WH + n * PADK + k0 + kp;
                bh[0] = *(const uint32_t*)(wr);
                bh[1] = *(const uint32_t*)(wr + 8);
                const uint16_t* wl = WL + n * PADK + k0 + kp;
                bl[0] = *(const uint32_t*)(wl);
                bl[1] = *(const uint32_t*)(wl + 8);
                mma_bf16(d[nt], ah, bh);
                mma_bf16(d[nt], ah, bl);
                mma_bf16(d[nt], al, bh);
            }
        }

        // ---- epilogue: STG.128 via lane pairing + BN stats ----
        {
            int row = tbase + warp_r * 16 + g8;
            #pragma unroll
            for (int nt = 0; nt < 8; nt++) {
                float* dd = d[nt];
                if (row < NODES) {
                    csum[nt * 2]     += dd[0]; csq[nt * 2]     += dd[0] * dd[0];
                    csum[nt * 2 + 1] += dd[1]; csq[nt * 2 + 1] += dd[1] * dd[1];
                }
                if (row + 8 < NODES) {
                    csum[nt * 2]     += dd[2]; csq[nt * 2]     += dd[2] * dd[2];
                    csum[nt * 2 + 1] += dd[3]; csq[nt * 2 + 1] += dd[3] * dd[3];
                }
                float tx = (lane & 1) ? dd[0] : dd[2];
                float ty = (lane & 1) ? dd[1] : dd[3];
                float rx = __shfl_xor_sync(0xffffffffu, tx, 1);
                float ry = __shfl_xor_sync(0xffffffffu, ty, 1);
                if (!(lane & 1)) {   // kp in {0,4}: store row r, cols kp..kp+3
                    if (row < NODES) {
                        int col = warp_c * 64 + nt * 8 + kp;
                        *(float4*)(out + (size_t)row * D + col) =
                            make_float4(dd[0], dd[1], rx, ry);
                    }
                } else {             // kp in {2,6}: store row r+8, cols kp-2..kp+1
                    if (row + 8 < NODES) {
                        int col = warp_c * 64 + nt * 8 + kp - 2;
                        *(float4*)(out + (size_t)(row + 8) * D + col) =
                            make_float4(rx, ry, dd[2], dd[3]);
                    }
                }
            }
        }
        __syncthreads();   // Z smem reusable next tile
    }

    // ---- stats: reduce over the 8 lanes sharing each column, then atomics ----
    #pragma unroll
    for (int i = 0; i < 16; i++) {
        float s = csum[i], q = csq[i];
        s += __shfl_xor_sync(0xffffffffu, s, 4);
        s += __shfl_xor_sync(0xffffffffu, s, 8);
        s += __shfl_xor_sync(0xffffffffu, s, 16);
        q += __shfl_xor_sync(0xffffffffu, q, 4);
        q += __shfl_xor_sync(0xffffffffu, q, 8);
        q += __shfl_xor_sync(0xffffffffu, q, 16);
        if (lane < 4) {
            int col = warp_c * 64 + (i >> 1) * 8 + lane * 2 + (i & 1);
            atomicAdd(&g_stats[STATS_OFF + col], s);
            atomicAdd(&g_stats[STATS_OFF + D + col], q);
        }
    }
}

// ---------------------- residual: h += relu(bn2(t2)) (BN computed in-block)
__global__ void __launch_bounds__(256)
residual_kernel(const float* __restrict__ t2, float* __restrict__ out_node,
                const float* __restrict__ gamma, const float* __restrict__ beta) {
    __shared__ float ss[256];
    int tid = threadIdx.x;
    if (tid < D) {
        float m = g_stats[2 * D + tid] * (1.0f / NODES);
        float v = g_stats[3 * D + tid] * (1.0f / NODES) - m * m;
        float sc = gamma[tid] * rsqrtf(v + BN_EPS);
        ss[tid] = sc;
        ss[D + tid] = beta[tid] - m * sc;
    }
    __syncthreads();
    int i = blockIdx.x * blockDim.x + tid;   // float4 index
    if (i >= NODES * (D / 4)) return;
    int c4 = (i & 31) * 4;
    float4 sc = *(const float4*)&ss[c4];
    float4 sh = *(const float4*)&ss[D + c4];
    float4 t = ((const float4*)t2)[i];
    float4 h = ((float4*)g_H)[i];
    h.x += fmaxf(fmaf(sc.x, t.x, sh.x), 0.f);
    h.y += fmaxf(fmaf(sc.y, t.y, sh.y), 0.f);
    h.z += fmaxf(fmaf(sc.z, t.z, sh.z), 0.f);
    h.w += fmaxf(fmaf(sc.w, t.w, sh.w), 0.f);
    ((float4*)g_H)[i] = h;
    if (out_node) ((float4*)out_node)[i] = h;
}

// ------------------------------- fused mean pool (batch sorted) + projection
__global__ void poolproj_kernel(const int* __restrict__ batch,
                                const float* __restrict__ wp,
                                const float* __restrict__ bp,
                                float* __restrict__ out) {
    int g = blockIdx.x;
    int lo = 0, hi_s = NODES;
    while (lo < hi_s) { int mid = (lo + hi_s) >> 1; if (batch[mid] < g) lo = mid + 1; else hi_s = mid; }
    int start = lo;
    lo = 0; hi_s = NODES;
    while (lo < hi_s) { int mid = (lo + hi_s) >> 1; if (batch[mid] < g + 1) lo = mid + 1; else hi_s = mid; }
    int end = lo;

    __shared__ float part[256];
    __shared__ float prow[D];
    int col = threadIdx.x & 127;
    int half = threadIdx.x >> 7;   // 0/1
    float s = 0.f;
    for (int row = start + half; row < end; row += 2)
        s += g_H[(size_t)row * D + col];
    part[threadIdx.x] = s;
    __syncthreads();
    if (threadIdx.x < 128) {
        float tot = part[threadIdx.x] + part[threadIdx.x + 128];
        float cnt = (float)(end - start);
        prow[threadIdx.x] = tot / fmaxf(cnt, 1.f);
    }
    __syncthreads();
    int c = threadIdx.x;   // 0..255
    float acc = bp[c];
    #pragma unroll
    for (int k = 0; k < D; k++) acc = fmaf(prow[k], wp[k * ODIM + c], acc);
    out[g * ODIM + c] = acc;
}

// ================================================================= launch
extern "C" void kernel_launch(void* const* d_in, const int* in_sizes, int n_in,
                              void* d_out, int out_size) {
    const float* x        = (const float*)d_in[0];
    const int*   ei       = (const int*)d_in[1];     // int32
    const int*   batch    = (const int*)d_in[2];     // int32
    const float* w1       = (const float*)d_in[3];
    const float* b1       = (const float*)d_in[4];
    const float* gamma1   = (const float*)d_in[5];
    const float* beta1    = (const float*)d_in[6];
    const float* w2       = (const float*)d_in[7];
    const float* b2       = (const float*)d_in[8];
    const float* gamma_bn = (const float*)d_in[9];
    const float* beta_bn  = (const float*)d_in[10];
    const float* wp       = (const float*)d_in[11];
    const float* bp       = (const float*)d_in[12];
    float* out = (float*)d_out;

    float *H, *AGG, *T1;
    cudaGetSymbolAddress((void**)&H, g_H);
    cudaGetSymbolAddress((void**)&AGG, g_AGG);
    cudaGetSymbolAddress((void**)&T1, g_T1);

    cudaFuncSetAttribute(tgemm_kernel<0, 0>,
                         cudaFuncAttributeMaxDynamicSharedMemorySize, TS_SMEM);
    cudaFuncSetAttribute(tgemm_kernel<1, 2 * D>,
                         cudaFuncAttributeMaxDynamicSharedMemorySize, TS_SMEM);

    const int n4 = NODES * (D / 4);
    const int cpGrid = (n4 + 255) / 256;
    const int edgeGrid = (EDGES + 255) / 256;

    // h = x
    init_kernel<<<cpGrid, 256>>>(x, n4);

    // ---- build CSR (dst -> list of src), once per launch ----
    zero_deg_kernel<<<NB, 256>>>();
    hist_kernel<<<edgeGrid, 256>>>(ei);
    blocksum_kernel<<<NB, 256>>>();
    scan_bsum_kernel<<<1, 512>>>();
    scan_local_kernel<<<NB, 256>>>();
    fill_kernel<<<edgeGrid, 256>>>(ei);

    for (int i = 0; i < LAYERS; i++) {
        // z = h + sum_neighbors (CSR gather, no atomics); zeroes stats
        gather_kernel<<<(NODES * 32 + 255) / 256, 256>>>();
        // t1 = z @ w1 + b1  (tensor cores; stats -> sum1/sq1)
        tgemm_kernel<0, 0><<<GEMM_GRID, 256, TS_SMEM>>>(
            AGG, w1 + i * D * D, b1 + i * D, T1, nullptr, nullptr);
        // t2 = relu(bn1(t1)) @ w2 + b2  (bn1 computed in prologue; stats -> sum2/sq2)
        tgemm_kernel<1, 2 * D><<<GEMM_GRID, 256, TS_SMEM>>>(
            T1, w2 + i * D * D, b2 + i * D, AGG, gamma1 + i * D, beta1 + i * D);
        // h += relu(bn2(t2)) (bn2 computed in-block); last layer writes node_emb
        float* out_node = (i == LAYERS - 1) ? (out + GRAPHS * ODIM) : nullptr;
        residual_kernel<<<cpGrid, 256>>>(AGG, out_node, gamma_bn + i * D, beta_bn + i * D);
    }

    poolproj_kernel<<<GRAPHS, 256>>>(batch, wp, bp, out);
}

// round 17
// speedup vs baseline: 1.1825x; 1.0898x over previous
#include <cuda_runtime.h>
#include <cstdint>

#define NODES 100000
#define EDGES 1600000
#define GRAPHS 64
#define D 128
#define ODIM 256
#define LAYERS 5
#define BN_EPS 1e-5f
#define NB 391                 // ceil(NODES/256) scan blocks

#define NTILES ((NODES + 127) / 128)   // 782
#define GEMM_GRID 148
#define PADK 136               // bf16 row stride (words of 2B)
#define PADF 132               // fp32 Z row stride (floats); 132*4=528B, 16B aligned

// dynamic smem layout (bytes)
#define OFF_SS    0                      // 256 floats (scale1|shift1)
#define OFF_BIAS  1024                   // 128 floats
#define OFF_WH    2048                   // Wt hi  [128][PADK] bf16 = 34816B
#define OFF_WL    (OFF_WH + 34816)
#define OFF_Z0    (OFF_WL + 34816)      // fp32 Z tile [128][PADF] = 67584B
#define OFF_Z1    (OFF_Z0 + 67584)
#define TS_SMEM   (OFF_Z1 + 67584)      // 206848 (~202KB) -> 1 CTA/SM

// Scratch (device globals; no runtime allocation)
__device__ float g_H[NODES * D];
__device__ float g_AGG[NODES * D];
__device__ float g_T1[NODES * D];
__device__ float g_stats[4 * D];     // [sum1 | sq1 | sum2 | sq2]
// CSR scratch
__device__ int g_deg[NODES];
__device__ int g_rowstart[NODES + 1];
__device__ int g_cursor[NODES];
__device__ int g_csr[EDGES];
__device__ int g_bsum[NB];
__device__ int g_boff[NB];

// ------------------------------------------------------------ bf16 helpers
__device__ __forceinline__ uint32_t pack_bf2(float a, float b) {   // low=a, high=b
    uint32_t r; asm("cvt.rn.bf16x2.f32 %0, %1, %2;" : "=r"(r) : "f"(b), "f"(a)); return r;
}
__device__ __forceinline__ float bflo(uint32_t h) { return __uint_as_float(h << 16); }
__device__ __forceinline__ float bfhi(uint32_t h) { return __uint_as_float(h & 0xffff0000u); }

__device__ __forceinline__ void mma_bf16(float* d, const uint32_t* a, const uint32_t* b) {
    asm volatile(
        "mma.sync.aligned.m16n8k16.row.col.f32.bf16.bf16.f32 "
        "{%0,%1,%2,%3}, {%4,%5,%6,%7}, {%8,%9}, {%0,%1,%2,%3};"
        : "+f"(d[0]), "+f"(d[1]), "+f"(d[2]), "+f"(d[3])
        : "r"(a[0]), "r"(a[1]), "r"(a[2]), "r"(a[3]), "r"(b[0]), "r"(b[1]));
}

__device__ __forceinline__ uint32_t smem_u32(const void* p) {
    uint32_t a;
    asm("{ .reg .u64 t; cvta.to.shared.u64 t, %1; cvt.u32.u64 %0, t; }"
        : "=r"(a) : "l"(p));
    return a;
}
__device__ __forceinline__ void cp_async16(uint32_t dst, const void* src, int srcsize) {
    asm volatile("cp.async.cg.shared.global [%0], [%1], 16, %2;"
                 :: "r"(dst), "l"(src), "r"(srcsize) : "memory");
}
#define CP_COMMIT() asm volatile("cp.async.commit_group;" ::: "memory")
#define CP_WAIT0()  asm volatile("cp.async.wait_group 0;" ::: "memory")

// ---------------------------------------------------------------- utilities
__global__ void init_kernel(const float* __restrict__ src, int n4) {
    int i = blockIdx.x * blockDim.x + threadIdx.x;
    if (i < n4) ((float4*)g_H)[i] = ((const float4*)src)[i];
}

// ------------------------------------------------------------- CSR build
__global__ void zero_deg_kernel() {
    int i = blockIdx.x * blockDim.x + threadIdx.x;
    if (i < NODES) g_deg[i] = 0;
}
__global__ void hist_kernel(const int* __restrict__ ei) {
    int e = blockIdx.x * blockDim.x + threadIdx.x;
    if (e < EDGES) atomicAdd(&g_deg[ei[EDGES + e]], 1);
}
__global__ void blocksum_kernel() {
    __shared__ int s[256];
    int i = blockIdx.x * 256 + threadIdx.x;
    int v = (i < NODES) ? g_deg[i] : 0;
    s[threadIdx.x] = v;
    __syncthreads();
    for (int off = 128; off > 0; off >>= 1) {
        if (threadIdx.x < off) s[threadIdx.x] += s[threadIdx.x + off];
        __syncthreads();
    }
    if (threadIdx.x == 0) g_bsum[blockIdx.x] = s[0];
}
__global__ void scan_bsum_kernel() {
    __shared__ int s[512];
    int t = threadIdx.x;
    int v = (t < NB) ? g_bsum[t] : 0;
    s[t] = v;
    __syncthreads();
    for (int off = 1; off < 512; off <<= 1) {
        int x = (t >= off) ? s[t - off] : 0;
        __syncthreads();
        s[t] += x;
        __syncthreads();
    }
    if (t < NB) g_boff[t] = s[t] - v;   // exclusive
}
__global__ void scan_local_kernel() {
    __shared__ int s[256];
    int i = blockIdx.x * 256 + threadIdx.x;
    int t = threadIdx.x;
    int v = (i < NODES) ? g_deg[i] : 0;
    s[t] = v;
    __syncthreads();
    for (int off = 1; off < 256; off <<= 1) {
        int x = (t >= off) ? s[t - off] : 0;
        __syncthreads();
        s[t] += x;
        __syncthreads();
    }
    if (i < NODES) {
        int start = g_boff[blockIdx.x] + s[t] - v;
        g_rowstart[i] = start;
        g_cursor[i] = start;
    }
    if (blockIdx.x == 0 && t == 0) g_rowstart[NODES] = EDGES;
}
__global__ void fill_kernel(const int* __restrict__ ei) {
    int e = blockIdx.x * blockDim.x + threadIdx.x;
    if (e < EDGES) {
        int dst = ei[EDGES + e];
        int p = atomicAdd(&g_cursor[dst], 1);
        g_csr[p] = ei[e];
    }
}

// --------------------------------------------- gather: z = h + sum(neighbors)
// also zeroes the BN stats accumulators for this layer (block 0)
__global__ void __launch_bounds__(256) gather_kernel() {
    if (blockIdx.x == 0) {
        int t = threadIdx.x;
        g_stats[t] = 0.f;
        g_stats[t + 256] = 0.f;
    }
    int gw = (blockIdx.x * blockDim.x + threadIdx.x) >> 5;
    if (gw >= NODES) return;
    int lane = threadIdx.x & 31;
    int s = g_rowstart[gw];
    int e = g_rowstart[gw + 1];
    float4 acc = *(const float4*)(g_H + (size_t)gw * D + lane * 4);
    for (int base = s; base < e; base += 32) {
        int n = min(32, e - base);
        int myidx = (base + lane < e) ? g_csr[base + lane] : 0;
        for (int t = 0; t < n; t++) {
            int src = __shfl_sync(0xffffffffu, myidx, t);
            float4 v = *(const float4*)(g_H + (size_t)src * D + lane * 4);
            acc.x += v.x; acc.y += v.y; acc.z += v.z; acc.w += v.w;
        }
    }
    *(float4*)(g_AGG + (size_t)gw * D + lane * 4) = acc;
}

// =============================================== tensor-core GEMM (mma.sync, bf16 x3)
// out[r][c] = bias[c] + sum_k act(in[r][k]) * w[k][c]
// Z staged as raw fp32 via cp.async (double-buffered; overlaps MMA of prev tile).
// hi/lo bf16 split + ACT (bn/relu) fused into the K loop at fragment load.
// 3 passes: AhBh + AhBl + AlBh, fp32 accum. Fused bias + BN column stats.
// ACT=1: computes scale/shift from g_stats[0..255] + gamma/beta in prologue.
template <int ACT, int STATS_OFF>
__global__ void __launch_bounds__(256)
tgemm_kernel(const float* __restrict__ in, const float* __restrict__ w,
             const float* __restrict__ bias, float* __restrict__ out,
             const float* __restrict__ gamma, const float* __restrict__ beta) {
    extern __shared__ char smem[];
    const int tid = threadIdx.x;
    const int wid = tid >> 5;
    const int lane = tid & 31;
    const int g8 = lane >> 2;          // 0..7
    const int kp = (lane & 3) * 2;     // 0,2,4,6

    uint16_t* WH = (uint16_t*)(smem + OFF_WH);
    uint16_t* WL = (uint16_t*)(smem + OFF_WL);
    float* Zb[2] = {(float*)(smem + OFF_Z0), (float*)(smem + OFF_Z1)};
    const uint32_t zb_u32[2] = {smem_u32(smem + OFF_Z0), smem_u32(smem + OFF_Z1)};
    float* biasS = (float*)(smem + OFF_BIAS);
    float* ssS   = (float*)(smem + OFF_SS);

    if (ACT && tid < D) {
        float m = g_stats[tid] * (1.0f / NODES);
        float v = g_stats[D + tid] * (1.0f / NODES) - m * m;
        float sc = gamma[tid] * rsqrtf(v + BN_EPS);
        ssS[tid] = sc;
        ssS[D + tid] = beta[tid] - m * sc;
    }
    if (tid < D) biasS[tid] = bias[tid];

    // ---- W prologue: transpose + hi/lo bf16 split (once per CTA) ----
    {
        const int c = tid & 127;
        const int khW = (tid >> 7) << 6;    // 0 or 64
        #pragma unroll 8
        for (int i = 0; i < 32; i++) {
            int k = khW + 2 * i;
            float w0 = w[(size_t)k * D + c];
            float w1 = w[(size_t)(k + 1) * D + c];
            uint32_t h = pack_bf2(w0, w1);
            uint32_t l = pack_bf2(w0 - bflo(h), w1 - bfhi(h));
            *(uint32_t*)(WH + c * PADK + k) = h;
            *(uint32_t*)(WL + c * PADK + k) = l;
        }
    }

    const int warp_r = wid >> 1;        // 0..3  (row group of 32)
    const int warp_c = wid & 1;         // 0..1  (col group of 64)
    const int srow = tid >> 1;          // staging row 0..127
    const int scol = (tid & 1) * 16;    // staging float4 col base (0 or 16)

    float csum[16], csq[16];
    #pragma unroll
    for (int i = 0; i < 16; i++) { csum[i] = 0.f; csq[i] = 0.f; }

    // ---- prologue: issue cp.async for first tile into buffer 0 ----
    {
        int row = blockIdx.x * 128 + srow;
        int ss_bytes = (row < NODES) ? 16 : 0;
        const float* gsrc = in + (size_t)min(row, NODES - 1) * D;
        uint32_t zdst = zb_u32[0] + srow * (PADF * 4);
        #pragma unroll
        for (int j = 0; j < 16; j++) {
            int c4 = scol + j;
            cp_async16(zdst + c4 * 16, gsrc + c4 * 4, ss_bytes);
        }
        CP_COMMIT();
    }

    int cur = 0;
    for (int tile = blockIdx.x; tile < NTILES; tile += GEMM_GRID, cur ^= 1) {
        const int tbase = tile * 128;
        CP_WAIT0();
        __syncthreads();   // cur buffer ready; prev reads of other buffer done

        // ---- issue cp.async for next tile into other buffer (overlaps MMA) ----
        const int next = tile + GEMM_GRID;
        if (next < NTILES) {
            int row = next * 128 + srow;
            int ss_bytes = (row < NODES) ? 16 : 0;
            const float* gsrc = in + (size_t)min(row, NODES - 1) * D;
            uint32_t zdst = zb_u32[cur ^ 1] + srow * (PADF * 4);
            #pragma unroll
            for (int j = 0; j < 16; j++) {
                int c4 = scol + j;
                cp_async16(zdst + c4 * 16, gsrc + c4 * 4, ss_bytes);
            }
        }
        CP_COMMIT();

        const float* ZF = Zb[cur];

        // ---- init D with bias ----
        float d[2][8][4];
        #pragma unroll
        for (int nt = 0; nt < 8; nt++) {
            float2 bv = *(const float2*)(biasS + warp_c * 64 + nt * 8 + kp);
            #pragma unroll
            for (int mt = 0; mt < 2; mt++) {
                d[mt][nt][0] = bv.x; d[mt][nt][1] = bv.y;
                d[mt][nt][2] = bv.x; d[mt][nt][3] = bv.y;
            }
        }

        // ---- K loop: 8 chunks of 16; fp32->bf16 split at frag load ----
        const int ra = warp_r * 32 + g8;
        #pragma unroll 2
        for (int kc = 0; kc < 8; kc++) {
            const int k0 = kc * 16;
            float2 sA0, sB0, sA1, sB1;
            if (ACT) {
                sA0 = *(const float2*)(ssS + k0 + kp);
                sB0 = *(const float2*)(ssS + 128 + k0 + kp);
                sA1 = *(const float2*)(ssS + k0 + kp + 8);
                sB1 = *(const float2*)(ssS + 128 + k0 + kp + 8);
            }
            uint32_t ah[2][4], al[2][4];
            #pragma unroll
            for (int mt = 0; mt < 2; mt++) {
                const float* zr = ZF + (ra + mt * 16) * PADF + k0 + kp;
                float2 f0 = *(const float2*)(zr);                 // row g8,   k kp
                float2 f1 = *(const float2*)(zr + 8 * PADF);      // row g8+8, k kp
                float2 f2 = *(const float2*)(zr + 8);             // row g8,   k kp+8
                float2 f3 = *(const float2*)(zr + 8 * PADF + 8);  // row g8+8, k kp+8
                if (ACT) {
                    f0.x = fmaxf(fmaf(sA0.x, f0.x, sB0.x), 0.f);
                    f0.y = fmaxf(fmaf(sA0.y, f0.y, sB0.y), 0.f);
                    f1.x = fmaxf(fmaf(sA0.x, f1.x, sB0.x), 0.f);
                    f1.y = fmaxf(fmaf(sA0.y, f1.y, sB0.y), 0.f);
                    f2.x = fmaxf(fmaf(sA1.x, f2.x, sB1.x), 0.f);
                    f2.y = fmaxf(fmaf(sA1.y, f2.y, sB1.y), 0.f);
                    f3.x = fmaxf(fmaf(sA1.x, f3.x, sB1.x), 0.f);
                    f3.y = fmaxf(fmaf(sA1.y, f3.y, sB1.y), 0.f);
                }
                uint32_t h;
                h = pack_bf2(f0.x, f0.y); ah[mt][0] = h;
                al[mt][0] = pack_bf2(f0.x - bflo(h), f0.y - bfhi(h));
                h = pack_bf2(f1.x, f1.y); ah[mt][1] = h;
                al[mt][1] = pack_bf2(f1.x - bflo(h), f1.y - bfhi(h));
                h = pack_bf2(f2.x, f2.y); ah[mt][2] = h;
                al[mt][2] = pack_bf2(f2.x - bflo(h), f2.y - bfhi(h));
                h = pack_bf2(f3.x, f3.y); ah[mt][3] = h;
                al[mt][3] = pack_bf2(f3.x - bflo(h), f3.y - bfhi(h));
            }
            #pragma unroll
            for (int nt = 0; nt < 8; nt++) {
                int n = warp_c * 64 + nt * 8 + g8;
                uint32_t bh[2], bl[2];
                const uint16_t* wr = WH + n * PADK + k0 + kp;
                bh[0] = *(const uint32_t*)(wr);
                bh[1] = *(const uint32_t*)(wr + 8);
                const uint16_t* wl = WL + n * PADK + k0 + kp;
                bl[0] = *(const uint32_t*)(wl);
                bl[1] = *(const uint32_t*)(wl + 8);
                mma_bf16(d[0][nt], ah[0], bh);
                mma_bf16(d[1][nt], ah[1], bh);
                mma_bf16(d[0][nt], ah[0], bl);
                mma_bf16(d[1][nt], ah[1], bl);
                mma_bf16(d[0][nt], al[0], bh);
                mma_bf16(d[1][nt], al[1], bh);
            }
        }

        // ---- epilogue: STG.128 via lane pairing + BN stats ----
        #pragma unroll
        for (int mt = 0; mt < 2; mt++) {
            int row = tbase + warp_r * 32 + mt * 16 + g8;
            #pragma unroll
            for (int nt = 0; nt < 8; nt++) {
                float* dd = d[mt][nt];
                if (row < NODES) {
                    csum[nt * 2]     += dd[0]; csq[nt * 2]     += dd[0] * dd[0];
                    csum[nt * 2 + 1] += dd[1]; csq[nt * 2 + 1] += dd[1] * dd[1];
                }
                if (row + 8 < NODES) {
                    csum[nt * 2]     += dd[2]; csq[nt * 2]     += dd[2] * dd[2];
                    csum[nt * 2 + 1] += dd[3]; csq[nt * 2 + 1] += dd[3] * dd[3];
                }
                float tx = (lane & 1) ? dd[0] : dd[2];
                float ty = (lane & 1) ? dd[1] : dd[3];
                float rx = __shfl_xor_sync(0xffffffffu, tx, 1);
                float ry = __shfl_xor_sync(0xffffffffu, ty, 1);
                if (!(lane & 1)) {   // kp in {0,4}: store row r, cols kp..kp+3
                    if (row < NODES) {
                        int col = warp_c * 64 + nt * 8 + kp;
                        *(float4*)(out + (size_t)row * D + col) =
                            make_float4(dd[0], dd[1], rx, ry);
                    }
                } else {             // kp in {2,6}: store row r+8, cols kp-2..kp+1
                    if (row + 8 < NODES) {
                        int col = warp_c * 64 + nt * 8 + kp - 2;
                        *(float4*)(out + (size_t)(row + 8) * D + col) =
                            make_float4(rx, ry, dd[2], dd[3]);
                    }
                }
            }
        }
    }

    // ---- stats: reduce over the 8 lanes sharing each column, then atomics ----
    #pragma unroll
    for (int i = 0; i < 16; i++) {
        float s = csum[i], q = csq[i];
        s += __shfl_xor_sync(0xffffffffu, s, 4);
        s += __shfl_xor_sync(0xffffffffu, s, 8);
        s += __shfl_xor_sync(0xffffffffu, s, 16);
        q += __shfl_xor_sync(0xffffffffu, q, 4);
        q += __shfl_xor_sync(0xffffffffu, q, 8);
        q += __shfl_xor_sync(0xffffffffu, q, 16);
        if (lane < 4) {
            int col = warp_c * 64 + (i >> 1) * 8 + lane * 2 + (i & 1);
            atomicAdd(&g_stats[STATS_OFF + col], s);
            atomicAdd(&g_stats[STATS_OFF + D + col], q);
        }
    }
}

// ---------------------- residual: h += relu(bn2(t2)) (BN computed in-block)
__global__ void __launch_bounds__(256)
residual_kernel(const float* __restrict__ t2, float* __restrict__ out_node,
                const float* __restrict__ gamma, const float* __restrict__ beta) {
    __shared__ float ss[256];
    int tid = threadIdx.x;
    if (tid < D) {
        float m = g_stats[2 * D + tid] * (1.0f / NODES);
        float v = g_stats[3 * D + tid] * (1.0f / NODES) - m * m;
        float sc = gamma[tid] * rsqrtf(v + BN_EPS);
        ss[tid] = sc;
        ss[D + tid] = beta[tid] - m * sc;
    }
    __syncthreads();
    int i = blockIdx.x * blockDim.x + tid;   // float4 index
    if (i >= NODES * (D / 4)) return;
    int c4 = (i & 31) * 4;
    float4 sc = *(const float4*)&ss[c4];
    float4 sh = *(const float4*)&ss[D + c4];
    float4 t = ((const float4*)t2)[i];
    float4 h = ((float4*)g_H)[i];
    h.x += fmaxf(fmaf(sc.x, t.x, sh.x), 0.f);
    h.y += fmaxf(fmaf(sc.y, t.y, sh.y), 0.f);
    h.z += fmaxf(fmaf(sc.z, t.z, sh.z), 0.f);
    h.w += fmaxf(fmaf(sc.w, t.w, sh.w), 0.f);
    ((float4*)g_H)[i] = h;
    if (out_node) ((float4*)out_node)[i] = h;
}

// ------------------------------- fused mean pool (batch sorted) + projection
__global__ void poolproj_kernel(const int* __restrict__ batch,
                                const float* __restrict__ wp,
                                const float* __restrict__ bp,
                                float* __restrict__ out) {
    int g = blockIdx.x;
    int lo = 0, hi_s = NODES;
    while (lo < hi_s) { int mid = (lo + hi_s) >> 1; if (batch[mid] < g) lo = mid + 1; else hi_s = mid; }
    int start = lo;
    lo = 0; hi_s = NODES;
    while (lo < hi_s) { int mid = (lo + hi_s) >> 1; if (batch[mid] < g + 1) lo = mid + 1; else hi_s = mid; }
    int end = lo;

    __shared__ float part[256];
    __shared__ float prow[D];
    int col = threadIdx.x & 127;
    int half = threadIdx.x >> 7;   // 0/1
    float s = 0.f;
    for (int row = start + half; row < end; row += 2)
        s += g_H[(size_t)row * D + col];
    part[threadIdx.x] = s;
    __syncthreads();
    if (threadIdx.x < 128) {
        float tot = part[threadIdx.x] + part[threadIdx.x + 128];
        float cnt = (float)(end - start);
        prow[threadIdx.x] = tot / fmaxf(cnt, 1.f);
    }
    __syncthreads();
    int c = threadIdx.x;   // 0..255
    float acc = bp[c];
    #pragma unroll
    for (int k = 0; k < D; k++) acc = fmaf(prow[k], wp[k * ODIM + c], acc);
    out[g * ODIM + c] = acc;
}

// ================================================================= launch
extern "C" void kernel_launch(void* const* d_in, const int* in_sizes, int n_in,
                              void* d_out, int out_size) {
    const float* x        = (const float*)d_in[0];
    const int*   ei       = (const int*)d_in[1];     // int32
    const int*   batch    = (const int*)d_in[2];     // int32
    const float* w1       = (const float*)d_in[3];
    const float* b1       = (const float*)d_in[4];
    const float* gamma1   = (const float*)d_in[5];
    const float* beta1    = (const float*)d_in[6];
    const float* w2       = (const float*)d_in[7];
    const float* b2       = (const float*)d_in[8];
    const float* gamma_bn = (const float*)d_in[9];
    const float* beta_bn  = (const float*)d_in[10];
    const float* wp       = (const float*)d_in[11];
    const float* bp       = (const float*)d_in[12];
    float* out = (float*)d_out;

    float *H, *AGG, *T1;
    cudaGetSymbolAddress((void**)&H, g_H);
    cudaGetSymbolAddress((void**)&AGG, g_AGG);
    cudaGetSymbolAddress((void**)&T1, g_T1);

    cudaFuncSetAttribute(tgemm_kernel<0, 0>,
                         cudaFuncAttributeMaxDynamicSharedMemorySize, TS_SMEM);
    cudaFuncSetAttribute(tgemm_kernel<1, 2 * D>,
                         cudaFuncAttributeMaxDynamicSharedMemorySize, TS_SMEM);

    const int n4 = NODES * (D / 4);
    const int cpGrid = (n4 + 255) / 256;
    const int edgeGrid = (EDGES + 255) / 256;

    // h = x
    init_kernel<<<cpGrid, 256>>>(x, n4);

    // ---- build CSR (dst -> list of src), once per launch ----
    zero_deg_kernel<<<NB, 256>>>();
    hist_kernel<<<edgeGrid, 256>>>(ei);
    blocksum_kernel<<<NB, 256>>>();
    scan_bsum_kernel<<<1, 512>>>();
    scan_local_kernel<<<NB, 256>>>();
    fill_kernel<<<edgeGrid, 256>>>(ei);

    for (int i = 0; i < LAYERS; i++) {
        // z = h + sum_neighbors (CSR gather, no atomics); zeroes stats
        gather_kernel<<<(NODES * 32 + 255) / 256, 256>>>();
        // t1 = z @ w1 + b1  (tensor cores; stats -> sum1/sq1)
        tgemm_kernel<0, 0><<<GEMM_GRID, 256, TS_SMEM>>>(
            AGG, w1 + i * D * D, b1 + i * D, T1, nullptr, nullptr);
        // t2 = relu(bn1(t1)) @ w2 + b2  (bn1 computed in prologue; stats -> sum2/sq2)
        tgemm_kernel<1, 2 * D><<<GEMM_GRID, 256, TS_SMEM>>>(
            T1, w2 + i * D * D, b2 + i * D, AGG, gamma1 + i * D, beta1 + i * D);
        // h += relu(bn2(t2)) (bn2 computed in-block); last layer writes node_emb
        float* out_node = (i == LAYERS - 1) ? (out + GRAPHS * ODIM) : nullptr;
        residual_kernel<<<cpGrid, 256>>>(AGG, out_node, gamma_bn + i * D, beta_bn + i * D);
    }

    poolproj_kernel<<<GRAPHS, 256>>>(batch, wp, bp, out);
}